// round 9
// baseline (speedup 1.0000x reference)
#include <cuda_runtime.h>

typedef unsigned long long u64;

#define Bn 8
#define Cn 64
#define Hn 128
#define Wn 128
#define PLANE (Hn * Wn)
#define NS 14

__device__ __forceinline__ u64 pk(float a, float b) {
    u64 r; asm("mov.b64 %0, {%1, %2};" : "=l"(r) : "f"(a), "f"(b)); return r;
}
__device__ __forceinline__ void unpk(u64 v, float& a, float& b) {
    asm("mov.b64 {%0, %1}, %2;" : "=f"(a), "=f"(b) : "l"(v));
}
__device__ __forceinline__ u64 fma2(u64 a, u64 b, u64 c) {
    u64 d; asm("fma.rn.f32x2 %0, %1, %2, %3;" : "=l"(d) : "l"(a), "l"(b), "l"(c)); return d;
}
__device__ __forceinline__ u64 add2(u64 a, u64 b) {
    u64 d; asm("add.rn.f32x2 %0, %1, %2;" : "=l"(d) : "l"(a), "l"(b)); return d;
}

__global__ void __launch_bounds__(256)
fused_kernel(const float* __restrict__ fe, const float* __restrict__ fu,
             float* __restrict__ out) {
    __shared__ u64 red[8][32][NS];
    __shared__ float Ssm[3][132];   // S row, indices 0..129 used (1-based px, zero pads)

    const int tid = threadIdx.x;
    const int w = tid >> 5, l = tid & 31;
    const int half = w & 1, cg = w >> 1;      // 8 warps = 4 channel groups x 2 half-rows
    const int b = blockIdx.x >> 7;            // 1024 blocks = 8 batches x 128 rows
    const int r = blockIdx.x & 127;
    const int x0 = half * 64 + l * 2;         // 2 pixels per thread
    const int c0 = cg * 16;
    const bool pm = (r > 0), pp = (r < Hn - 1);
    const bool needL = (l == 0) && (half == 1);    // needs fu(x=63)
    const bool needR = (l == 31) && (half == 0);   // needs fu(x=64)

    const size_t base = ((size_t)b * Cn + c0) * PLANE + (size_t)r * Wn + x0;
    const float* fup = fu + base;
    const float* fep = fe + base;

    // ---- Phase 1: accumulate cross terms X (center packed, L/R scalar), S, F ----
    u64 Xc[3], S2[3], F2 = 0ull;
    float Xl[3][2], Xr[3][2];
    #pragma unroll
    for (int dr = 0; dr < 3; ++dr) {
        Xc[dr] = 0ull; S2[dr] = 0ull;
        Xl[dr][0] = Xl[dr][1] = Xr[dr][0] = Xr[dr][1] = 0.f;
    }
    const float2 z2 = make_float2(0.f, 0.f);

    #pragma unroll 2
    for (int c = 0; c < 16; ++c) {
        const float* uc = fup + c * PLANE;
        float2 v0 = pm ? __ldg((const float2*)(uc - Wn)) : z2;
        float2 v1 = __ldg((const float2*)uc);
        float2 v2 = pp ? __ldg((const float2*)(uc + Wn)) : z2;
        float2 fv = __ldg((const float2*)(fep + c * PLANE));
        // Boundary columns (only lanes 0/31 of the relevant halves load; predicated)
        float eL0 = (needL && pm) ? __ldg(uc - Wn - 1) : 0.f;
        float eL1 = needL        ? __ldg(uc - 1)      : 0.f;
        float eL2 = (needL && pp) ? __ldg(uc + Wn - 1) : 0.f;
        float eR0 = (needR && pm) ? __ldg(uc - Wn + 2) : 0.f;
        float eR1 = needR        ? __ldg(uc + 2)      : 0.f;
        float eR2 = (needR && pp) ? __ldg(uc + Wn + 2) : 0.f;

        u64 fp2 = pk(fv.x, fv.y);
        F2 = fma2(fp2, fp2, F2);

        float2 vv[3] = {v0, v1, v2};
        float eLs[3] = {eL0, eL1, eL2};
        float eRs[3] = {eR0, eR1, eR2};
        #pragma unroll
        for (int dr = 0; dr < 3; ++dr) {
            float2 v = vv[dr];
            float L = __shfl_up_sync(0xffffffffu, v.y, 1);
            float R = __shfl_down_sync(0xffffffffu, v.x, 1);
            if (l == 0)  L = eLs[dr];
            if (l == 31) R = eRs[dr];
            u64 cp = pk(v.x, v.y);
            S2[dr] = fma2(cp, cp, S2[dr]);
            Xc[dr] = fma2(cp, fp2, Xc[dr]);
            Xl[dr][0] = fmaf(L,   fv.x, Xl[dr][0]);
            Xl[dr][1] = fmaf(v.x, fv.y, Xl[dr][1]);
            Xr[dr][0] = fmaf(v.y, fv.x, Xr[dr][0]);
            Xr[dr][1] = fmaf(R,   fv.y, Xr[dr][1]);
        }
    }

    // ---- Cross-warp reduction over the 4 channel groups of this half ----
    {
        u64* s = red[w][l];
        #pragma unroll
        for (int dr = 0; dr < 3; ++dr) {
            s[dr]     = Xc[dr];
            s[3 + dr] = pk(Xl[dr][0], Xl[dr][1]);
            s[6 + dr] = pk(Xr[dr][0], Xr[dr][1]);
            s[9 + dr] = S2[dr];
        }
        s[12] = F2;
    }
    if (tid < 3) { Ssm[tid][0] = 0.f; Ssm[tid][129] = 0.f; }
    __syncthreads();
    {
        const int h = half;
        #pragma unroll
        for (int dr = 0; dr < 3; ++dr) {
            Xc[dr] = add2(add2(red[h][l][dr],     red[h+2][l][dr]),
                          add2(red[h+4][l][dr],   red[h+6][l][dr]));
            u64 xl = add2(add2(red[h][l][3+dr],   red[h+2][l][3+dr]),
                          add2(red[h+4][l][3+dr], red[h+6][l][3+dr]));
            u64 xr = add2(add2(red[h][l][6+dr],   red[h+2][l][6+dr]),
                          add2(red[h+4][l][6+dr], red[h+6][l][6+dr]));
            S2[dr] = add2(add2(red[h][l][9+dr],   red[h+2][l][9+dr]),
                          add2(red[h+4][l][9+dr], red[h+6][l][9+dr]));
            unpk(xl, Xl[dr][0], Xl[dr][1]);
            unpk(xr, Xr[dr][0], Xr[dr][1]);
        }
        F2 = add2(add2(red[h][l][12],   red[h+2][l][12]),
                  add2(red[h+4][l][12], red[h+6][l][12]));
    }
    // Publish the S row (warps 0 and 1 cover both halves; values identical per half)
    if (w < 2) {
        #pragma unroll
        for (int dr = 0; dr < 3; ++dr) {
            float s0, s1; unpk(S2[dr], s0, s1);
            Ssm[dr][1 + x0] = s0;
            Ssm[dr][2 + x0] = s1;
        }
    }
    __syncthreads();

    // ---- Phase 2: distances + softmax -> weights ----
    float Xcs[3][2], Fs[2];
    #pragma unroll
    for (int dr = 0; dr < 3; ++dr) unpk(Xc[dr], Xcs[dr][0], Xcs[dr][1]);
    unpk(F2, Fs[0], Fs[1]);

    float wt[9][2];
    #pragma unroll
    for (int p = 0; p < 2; ++p) {
        float F = Fs[p];
        float s = 0.f;
        #pragma unroll
        for (int dr = 0; dr < 3; ++dr) {
            float Sm1 = Ssm[dr][x0 + p];        // S(x-1)
            float S0  = Ssm[dr][x0 + p + 1];    // S(x)
            float Sp1 = Ssm[dr][x0 + p + 2];    // S(x+1)
            float dl = sqrtf(fmaxf(fmaf(-2.f, Xl[dr][p],  Sm1 + F), 0.f));
            float dc = sqrtf(fmaxf(fmaf(-2.f, Xcs[dr][p], S0  + F), 0.f));
            float dRt = sqrtf(fmaxf(fmaf(-2.f, Xr[dr][p], Sp1 + F), 0.f));
            float el = __expf(-dl), ec = __expf(-dc), er = __expf(-dRt);
            wt[dr*3+0][p] = el; wt[dr*3+1][p] = ec; wt[dr*3+2][p] = er;
            s += el + ec + er;
        }
        float inv = 1.f / s;
        #pragma unroll
        for (int k = 0; k < 9; ++k) wt[k][p] *= inv;
    }
    u64 wc2[3];
    #pragma unroll
    for (int dr = 0; dr < 3; ++dr) wc2[dr] = pk(wt[dr*3+1][0], wt[dr*3+1][1]);

    // ---- Phase 3: weighted neighbor sum + fe -> out ----
    float* op = out + base;
    #pragma unroll 2
    for (int c = 0; c < 16; ++c) {
        const float* uc = fup + c * PLANE;
        float2 v0 = pm ? __ldg((const float2*)(uc - Wn)) : z2;
        float2 v1 = __ldg((const float2*)uc);
        float2 v2 = pp ? __ldg((const float2*)(uc + Wn)) : z2;
        float2 fv = __ldg((const float2*)(fep + c * PLANE));
        float eL0 = (needL && pm) ? __ldg(uc - Wn - 1) : 0.f;
        float eL1 = needL        ? __ldg(uc - 1)      : 0.f;
        float eL2 = (needL && pp) ? __ldg(uc + Wn - 1) : 0.f;
        float eR0 = (needR && pm) ? __ldg(uc - Wn + 2) : 0.f;
        float eR1 = needR        ? __ldg(uc + 2)      : 0.f;
        float eR2 = (needR && pp) ? __ldg(uc + Wn + 2) : 0.f;

        u64 acc = pk(fv.x, fv.y);
        float s0 = 0.f, s1 = 0.f;

        float2 vv[3] = {v0, v1, v2};
        float eLs[3] = {eL0, eL1, eL2};
        float eRs[3] = {eR0, eR1, eR2};
        #pragma unroll
        for (int dr = 0; dr < 3; ++dr) {
            float2 v = vv[dr];
            float L = __shfl_up_sync(0xffffffffu, v.y, 1);
            float R = __shfl_down_sync(0xffffffffu, v.x, 1);
            if (l == 0)  L = eLs[dr];
            if (l == 31) R = eRs[dr];
            u64 cp = pk(v.x, v.y);
            acc = fma2(cp, wc2[dr], acc);
            s0 = fmaf(L,   wt[dr*3+0][0], s0);
            s1 = fmaf(v.x, wt[dr*3+0][1], s1);
            s0 = fmaf(v.y, wt[dr*3+2][0], s0);
            s1 = fmaf(R,   wt[dr*3+2][1], s1);
        }
        float o0, o1; unpk(acc, o0, o1);
        float2 o = make_float2(o0 + s0, o1 + s1);
        *(float2*)(op + c * PLANE) = o;
    }
}

extern "C" void kernel_launch(void* const* d_in, const int* in_sizes, int n_in,
                              void* d_out, int out_size) {
    const float* fe = (const float*)d_in[0];   // fe_lv
    const float* fu = (const float*)d_in[1];   // fused_features
    float* out = (float*)d_out;

    fused_kernel<<<Bn * Hn, 256>>>(fe, fu, out);   // 1024 blocks x 256 threads
}

// round 11
// speedup vs baseline: 1.7190x; 1.7190x over previous
#include <cuda_runtime.h>

typedef unsigned long long u64;

#define Bn 8
#define Cn 64
#define Hn 128
#define Wn 128
#define PLANE (Hn * Wn)
#define NPAD 27

__device__ __forceinline__ u64 pk(float a, float b) {
    u64 r; asm("mov.b64 %0, {%1, %2};" : "=l"(r) : "f"(a), "f"(b)); return r;
}
__device__ __forceinline__ void unpk(u64 v, float& a, float& b) {
    asm("mov.b64 {%0, %1}, %2;" : "=f"(a), "=f"(b) : "l"(v));
}
__device__ __forceinline__ u64 fma2(u64 a, u64 b, u64 c) {
    u64 d; asm("fma.rn.f32x2 %0, %1, %2, %3;" : "=l"(d) : "l"(a), "l"(b), "l"(c)); return d;
}
__device__ __forceinline__ u64 add2(u64 a, u64 b) {
    u64 d; asm("add.rn.f32x2 %0, %1, %2;" : "=l"(d) : "l"(a), "l"(b)); return d;
}

__global__ void __launch_bounds__(64)
fused_kernel(const float* __restrict__ fe, const float* __restrict__ fu,
             float* __restrict__ out) {
    __shared__ u64 red[2][32][NPAD];

    const int tid = threadIdx.x;
    const int w = tid >> 5, l = tid & 31;     // 2 warps: channel groups of 32
    const int b = blockIdx.x >> 7;            // 1024 blocks = 8 batches x 128 rows
    const int r = blockIdx.x & 127;
    const int x0 = l * 4;
    const int c0 = w * 32;
    const bool pm = (r > 0), pp = (r < Hn - 1);

    const size_t base = ((size_t)b * Cn + c0) * PLANE + (size_t)r * Wn + x0;
    const float* fup = fu + base;
    const float* fep = fe + base;

    // ---------------- Phase 1: accumulate X (9 cross terms), S (3 rows), F ----------------
    u64 X2[9][2], S2[3][2], F2[2];
    #pragma unroll
    for (int k = 0; k < 9; ++k) { X2[k][0] = 0ull; X2[k][1] = 0ull; }
    #pragma unroll
    for (int d = 0; d < 3; ++d) { S2[d][0] = 0ull; S2[d][1] = 0ull; }
    F2[0] = 0ull; F2[1] = 0ull;

    const float4 z4 = make_float4(0.f, 0.f, 0.f, 0.f);

    #pragma unroll 4
    for (int c = 0; c < 32; ++c) {
        const float* uc = fup + c * PLANE;
        float4 vr[3];
        vr[0] = pm ? __ldg((const float4*)(uc - Wn)) : z4;
        vr[1] = __ldg((const float4*)uc);
        vr[2] = pp ? __ldg((const float4*)(uc + Wn)) : z4;
        float4 f4 = __ldg((const float4*)(fep + c * PLANE));

        u64 fe01 = pk(f4.x, f4.y), fe23 = pk(f4.z, f4.w);
        F2[0] = fma2(fe01, fe01, F2[0]);
        F2[1] = fma2(fe23, fe23, F2[1]);

        #pragma unroll
        for (int dr = 0; dr < 3; ++dr) {
            float4 v = vr[dr];
            float L = __shfl_up_sync(0xffffffffu, v.w, 1);   if (l == 0)  L = 0.f;
            float R = __shfl_down_sync(0xffffffffu, v.x, 1); if (l == 31) R = 0.f;
            u64 c01 = pk(v.x, v.y), c23 = pk(v.z, v.w);
            u64 l01 = pk(L, v.x),   yz  = pk(v.y, v.z), r23 = pk(v.w, R);

            S2[dr][0] = fma2(c01, c01, S2[dr][0]);
            S2[dr][1] = fma2(c23, c23, S2[dr][1]);

            X2[dr*3+0][0] = fma2(l01, fe01, X2[dr*3+0][0]);
            X2[dr*3+0][1] = fma2(yz,  fe23, X2[dr*3+0][1]);
            X2[dr*3+1][0] = fma2(c01, fe01, X2[dr*3+1][0]);
            X2[dr*3+1][1] = fma2(c23, fe23, X2[dr*3+1][1]);
            X2[dr*3+2][0] = fma2(yz,  fe01, X2[dr*3+2][0]);
            X2[dr*3+2][1] = fma2(r23, fe23, X2[dr*3+2][1]);
        }
    }

    // ---------------- Cross-warp reduction (sum the 2 channel groups) ----------------
    {
        u64* slot = red[w][l];
        #pragma unroll
        for (int k = 0; k < 9; ++k) { slot[2*k] = X2[k][0]; slot[2*k+1] = X2[k][1]; }
        #pragma unroll
        for (int d = 0; d < 3; ++d) { slot[18+2*d] = S2[d][0]; slot[19+2*d] = S2[d][1]; }
        slot[24] = F2[0]; slot[25] = F2[1];
    }
    __syncthreads();
    {
        #pragma unroll
        for (int k = 0; k < 9; ++k) {
            X2[k][0] = add2(red[0][l][2*k],   red[1][l][2*k]);
            X2[k][1] = add2(red[0][l][2*k+1], red[1][l][2*k+1]);
        }
        #pragma unroll
        for (int d = 0; d < 3; ++d) {
            S2[d][0] = add2(red[0][l][18+2*d], red[1][l][18+2*d]);
            S2[d][1] = add2(red[0][l][19+2*d], red[1][l][19+2*d]);
        }
        F2[0] = add2(red[0][l][24], red[1][l][24]);
        F2[1] = add2(red[0][l][25], red[1][l][25]);
    }

    // ---------------- Phase 2: distances + softmax -> packed weights ----------------
    float Xs[9][4], Ss[3][6], Fs[4];   // Ss[dr] = {L, s0, s1, s2, s3, R}
    #pragma unroll
    for (int k = 0; k < 9; ++k) {
        unpk(X2[k][0], Xs[k][0], Xs[k][1]);
        unpk(X2[k][1], Xs[k][2], Xs[k][3]);
    }
    #pragma unroll
    for (int d = 0; d < 3; ++d) {
        unpk(S2[d][0], Ss[d][1], Ss[d][2]);
        unpk(S2[d][1], Ss[d][3], Ss[d][4]);
        float SL = __shfl_up_sync(0xffffffffu, Ss[d][4], 1);   if (l == 0)  SL = 0.f;
        float SR = __shfl_down_sync(0xffffffffu, Ss[d][1], 1); if (l == 31) SR = 0.f;
        Ss[d][0] = SL; Ss[d][5] = SR;
    }
    unpk(F2[0], Fs[0], Fs[1]);
    unpk(F2[1], Fs[2], Fs[3]);

    u64 w2[9][2];
    float wtmp[9][4];
    #pragma unroll
    for (int p = 0; p < 4; ++p) {
        float F = Fs[p];
        float s = 0.f;
        #pragma unroll
        for (int dr = 0; dr < 3; ++dr) {
            #pragma unroll
            for (int dc = 0; dc < 3; ++dc) {
                float Sv = Ss[dr][p + dc];           // p+dc in [0,5]
                float d2 = fmaf(-2.f, Xs[dr*3+dc][p], Sv + F);
                float dd = sqrtf(fmaxf(d2, 0.f));
                float e = __expf(-dd);               // dist >= 0: no overflow, skip max-shift
                wtmp[dr*3+dc][p] = e;
                s += e;
            }
        }
        float inv = 1.f / s;
        #pragma unroll
        for (int k = 0; k < 9; ++k) wtmp[k][p] *= inv;
    }
    #pragma unroll
    for (int k = 0; k < 9; ++k) {
        w2[k][0] = pk(wtmp[k][0], wtmp[k][1]);
        w2[k][1] = pk(wtmp[k][2], wtmp[k][3]);
    }

    // ---------------- Phase 3: weighted neighbor sum + fe -> out ----------------
    float* op = out + base;
    #pragma unroll 2
    for (int c = 0; c < 32; ++c) {
        const float* uc = fup + c * PLANE;
        float4 vr[3];
        vr[0] = pm ? __ldg((const float4*)(uc - Wn)) : z4;
        vr[1] = __ldg((const float4*)uc);
        vr[2] = pp ? __ldg((const float4*)(uc + Wn)) : z4;
        float4 f4 = __ldg((const float4*)(fep + c * PLANE));

        u64 acc0 = pk(f4.x, f4.y);
        u64 acc1 = pk(f4.z, f4.w);
        #pragma unroll
        for (int dr = 0; dr < 3; ++dr) {
            float4 v = vr[dr];
            float L = __shfl_up_sync(0xffffffffu, v.w, 1);   if (l == 0)  L = 0.f;
            float R = __shfl_down_sync(0xffffffffu, v.x, 1); if (l == 31) R = 0.f;
            u64 c01 = pk(v.x, v.y), c23 = pk(v.z, v.w);
            u64 l01 = pk(L, v.x),   yz  = pk(v.y, v.z), r23 = pk(v.w, R);

            acc0 = fma2(l01, w2[dr*3+0][0], acc0);
            acc1 = fma2(yz,  w2[dr*3+0][1], acc1);
            acc0 = fma2(c01, w2[dr*3+1][0], acc0);
            acc1 = fma2(c23, w2[dr*3+1][1], acc1);
            acc0 = fma2(yz,  w2[dr*3+2][0], acc0);
            acc1 = fma2(r23, w2[dr*3+2][1], acc1);
        }
        float4 o4;
        unpk(acc0, o4.x, o4.y);
        unpk(acc1, o4.z, o4.w);
        *(float4*)(op + c * PLANE) = o4;
    }
}

extern "C" void kernel_launch(void* const* d_in, const int* in_sizes, int n_in,
                              void* d_out, int out_size) {
    const float* fe = (const float*)d_in[0];   // fe_lv
    const float* fu = (const float*)d_in[1];   // fused_features
    float* out = (float*)d_out;

    fused_kernel<<<Bn * Hn, 64>>>(fe, fu, out);   // 1024 blocks x 64 threads
}